// round 14
// baseline (speedup 1.0000x reference)
#include <cuda_runtime.h>

// CorrectedPartialCharges — ridge kernel (R6/R13, 10.72 us) + L2 access-policy
// window probe:
//   out[i] = x[i] + (total_charge[g] - sum_{j in g} x[j]) / n_atoms[g],  g = i / 256
//
// Kernel body unchanged from the proven ridge: one graph per 8-lane group,
// 8 front-batched LDG.128 per lane (MLP_p1=8), 3-stage xor-shuffle, 8x
// STG.128. Compulsory traffic: 33.5 MB read + 33.5 MB write through LTS per
// replay; warm loop is L2-resident and bound at ~6.25 TB/s of mixed R/W LTS
// throughput. This round's single variable: launch with an accessPolicyWindow
// marking the input as Persisting (bias L2 replacement in favor of the
// read stream). Falls back to a plain launch if the attributed launch fails.

static constexpr int ATOMS_PER_GRAPH   = 256;            // = 64 float4
static constexpr int THREADS_PER_BLOCK = 256;
static constexpr int GRAPHS_PER_BLOCK  = THREADS_PER_BLOCK / 8;   // 32

__global__ __launch_bounds__(THREADS_PER_BLOCK, 4)
void corrected_partial_charges_kernel(
    const float* __restrict__ node_outputs,   // [N]
    const float* __restrict__ total_charge,   // [B]
    const int*   __restrict__ n_atoms,        // [B]
    float*       __restrict__ out,            // [N]
    int n_graphs)
{
    const int tid   = threadIdx.x;
    const int lane8 = tid & 7;                 // lane within 8-lane group
    const int g     = blockIdx.x * GRAPHS_PER_BLOCK + (tid >> 3);
    if (g >= n_graphs) return;

    const size_t base = (size_t)g * ATOMS_PER_GRAPH;   // in floats
    const float4* __restrict__ in4 = reinterpret_cast<const float4*>(node_outputs + base);
    float4*       __restrict__ o4  = reinterpret_cast<float4*>(out + base);

    // 8 front-batched 16B loads per lane: graph spans float4 [0,64)
    float4 v[8];
    #pragma unroll
    for (int k = 0; k < 8; k++)
        v[k] = in4[lane8 + 8 * k];

    const float tc = __ldg(total_charge + g);
    const float na = (float)__ldg(n_atoms + g);

    float s = 0.0f;
    #pragma unroll
    for (int k = 0; k < 8; k++)
        s += ((v[k].x + v[k].y) + (v[k].z + v[k].w));

    // 3-stage butterfly within the aligned 8-lane group
    #pragma unroll
    for (int off = 4; off > 0; off >>= 1)
        s += __shfl_xor_sync(0xffffffffu, s, off);

    const float l = (tc - s) / na;

    #pragma unroll
    for (int k = 0; k < 8; k++) {
        v[k].x += l; v[k].y += l; v[k].z += l; v[k].w += l;
        o4[lane8 + 8 * k] = v[k];
    }
}

extern "C" void kernel_launch(void* const* d_in, const int* in_sizes, int n_in,
                              void* d_out, int out_size)
{
    // metadata order: node_outputs [N,1] f32, total_charge [B] f32,
    //                 batch [N] i32 (unused: structure static), n_atoms [B] i32
    const float* node_outputs = (const float*)d_in[0];
    const float* total_charge = (const float*)d_in[1];
    const int*   n_atoms      = (const int*)d_in[3];
    float*       out          = (float*)d_out;

    const int n_graphs = in_sizes[1];                 // 32768
    const int n_atoms_total = in_sizes[0];            // 8388608
    const int blocks = (n_graphs + GRAPHS_PER_BLOCK - 1) / GRAPHS_PER_BLOCK; // 1024

    // Attributed launch: persist the input stream in L2.
    cudaAccessPolicyWindow win = {};
    win.base_ptr  = const_cast<float*>(node_outputs);
    win.num_bytes = (size_t)n_atoms_total * sizeof(float);   // 33.5 MB
    win.hitRatio  = 1.0f;
    win.hitProp   = cudaAccessPropertyPersisting;
    win.missProp  = cudaAccessPropertyStreaming;

    cudaLaunchAttribute attr = {};
    attr.id = cudaLaunchAttributeAccessPolicyWindow;
    attr.val.accessPolicyWindow = win;

    cudaLaunchConfig_t cfg = {};
    cfg.gridDim  = dim3((unsigned)blocks, 1, 1);
    cfg.blockDim = dim3(THREADS_PER_BLOCK, 1, 1);
    cfg.dynamicSmemBytes = 0;
    cfg.stream = 0;
    cfg.attrs = &attr;
    cfg.numAttrs = 1;

    cudaError_t err = cudaLaunchKernelEx(&cfg, corrected_partial_charges_kernel,
                                         node_outputs, total_charge, n_atoms,
                                         out, n_graphs);
    if (err != cudaSuccess) {
        // Fallback: plain launch (identical kernel, no window)
        cudaGetLastError();  // clear
        corrected_partial_charges_kernel<<<blocks, THREADS_PER_BLOCK>>>(
            node_outputs, total_charge, n_atoms, out, n_graphs);
    }
}